// round 5
// baseline (speedup 1.0000x reference)
#include <cuda_runtime.h>
#include <math.h>
#include <stdint.h>

// Problem constants (AGDNConv_14173392077052)
#define NN   50000
#define EE   1600000
#define FIN  256
#define HH   2
#define DD   64
#define KK   3
#define HD   128          // H*D
#define NHH  (NN*HH)

// ---------------- scratch (device globals) ----------------------------------
__device__ float g_hsrc[NN * HD];
__device__ float g_hdst[NN * HD];
__device__ float g_h[2][NN * HD];
__device__ float g_hs[KK][NN * HD];
__device__ float g_asrc[NN * HH];
__device__ float g_adst[NN * HH];
__device__ float g_sum2[2 * NHH];          // [0,NHH): dst sums, [NHH,..): src sums
__device__ int   g_deg[NN];
__device__ int   g_off[NN + 1];
__device__ int   g_cur[NN];
__device__ float4 g_csr_ed[EE];            // {src(bits), ee0/a0, ee1/a1, pad}

__device__ __forceinline__ float wsum(float v) {
#pragma unroll
    for (int o = 16; o > 0; o >>= 1) v += __shfl_xor_sync(0xffffffffu, v, o);
    return v;
}
__device__ __forceinline__ float hsum16(float v) {
#pragma unroll
    for (int o = 8; o > 0; o >>= 1) v += __shfl_xor_sync(0xffffffffu, v, o);
    return v;
}
__device__ __forceinline__ float leaky(float x) { return x > 0.0f ? x : 0.2f * x; }

__device__ __forceinline__ uint32_t f2t(float x) {
    uint32_t r; asm("cvt.rna.tf32.f32 %0, %1;" : "=r"(r) : "f"(x)); return r;
}
__device__ __forceinline__ void mma_tf32(float* c, const uint32_t* a, const uint32_t* b) {
    asm volatile("mma.sync.aligned.m16n8k8.row.col.f32.tf32.tf32.f32 "
                 "{%0,%1,%2,%3}, {%4,%5,%6,%7}, {%8,%9}, {%0,%1,%2,%3};"
                 : "+f"(c[0]), "+f"(c[1]), "+f"(c[2]), "+f"(c[3])
                 : "r"(a[0]), "r"(a[1]), "r"(a[2]), "r"(a[3]), "r"(b[0]), "r"(b[1]));
}

// ---------------- tf32 tensor-core GEMM: 128x128 tile, BK=32 ----------------
#define SA 36
__global__ __launch_bounds__(256, 2) void gemm_tf32_kernel(const float* __restrict__ A,
                                                           const float* __restrict__ Wsrc,
                                                           const float* __restrict__ Wdst,
                                                           const float* __restrict__ bias) {
    __shared__ float As[128][SA];
    __shared__ float Bs[128][SA];
    const float* B = (blockIdx.y == 0) ? Wsrc : Wdst;
    float* C = (blockIdx.y == 0) ? g_hsrc : g_hdst;

    int tid = threadIdx.x, lane = tid & 31, wid = tid >> 5;
    int wm0 = (wid >> 2) * 64;
    int wn0 = (wid & 3) * 32;
    int g = lane >> 2, tig = lane & 3;
    int m0 = blockIdx.x * 128;

    float acc[4][4][4];
#pragma unroll
    for (int i = 0; i < 4; i++)
#pragma unroll
        for (int j = 0; j < 4; j++)
#pragma unroll
            for (int q = 0; q < 4; q++) acc[i][j][q] = 0.0f;

    for (int k0 = 0; k0 < FIN; k0 += 32) {
#pragma unroll
        for (int it = 0; it < 4; it++) {
            int idx = tid + it * 256;
            int row = idx >> 3, q = idx & 7;
            int gm = m0 + row;
            float4 v = make_float4(0.f, 0.f, 0.f, 0.f);
            if (gm < NN) v = *(const float4*)(A + (size_t)gm * FIN + k0 + q * 4);
            *(float4*)(&As[row][q * 4]) = v;
        }
#pragma unroll
        for (int it = 0; it < 4; it++) {
            int idx = tid + it * 256;
            int kr = idx >> 5, nq = idx & 31;
            float4 v = *(const float4*)(B + (size_t)(k0 + kr) * HD + nq * 4);
            Bs[nq * 4 + 0][kr] = v.x;
            Bs[nq * 4 + 1][kr] = v.y;
            Bs[nq * 4 + 2][kr] = v.z;
            Bs[nq * 4 + 3][kr] = v.w;
        }
        __syncthreads();

#pragma unroll
        for (int kk = 0; kk < 4; kk++) {
            int kb = kk * 8;
            uint32_t af[4][4], bf[4][2];
#pragma unroll
            for (int mt = 0; mt < 4; mt++) {
                int r = wm0 + mt * 16 + g;
                af[mt][0] = f2t(As[r][kb + tig]);
                af[mt][1] = f2t(As[r + 8][kb + tig]);
                af[mt][2] = f2t(As[r][kb + tig + 4]);
                af[mt][3] = f2t(As[r + 8][kb + tig + 4]);
            }
#pragma unroll
            for (int nt = 0; nt < 4; nt++) {
                int c = wn0 + nt * 8 + g;
                bf[nt][0] = f2t(Bs[c][kb + tig]);
                bf[nt][1] = f2t(Bs[c][kb + tig + 4]);
            }
#pragma unroll
            for (int mt = 0; mt < 4; mt++)
#pragma unroll
                for (int nt = 0; nt < 4; nt++)
                    mma_tf32(acc[mt][nt], af[mt], bf[nt]);
        }
        __syncthreads();
    }

    bool add_b = (blockIdx.y == 1);
#pragma unroll
    for (int mt = 0; mt < 4; mt++) {
        int r0 = m0 + wm0 + mt * 16 + g;
        int r1 = r0 + 8;
#pragma unroll
        for (int nt = 0; nt < 4; nt++) {
            int col = wn0 + nt * 8 + tig * 2;
            float2 v0 = make_float2(acc[mt][nt][0], acc[mt][nt][1]);
            float2 v1 = make_float2(acc[mt][nt][2], acc[mt][nt][3]);
            if (add_b) {
                float2 bb = *(const float2*)(bias + col);
                v0.x += bb.x; v0.y += bb.y; v1.x += bb.x; v1.y += bb.y;
            }
            if (r0 < NN) *(float2*)(C + (size_t)r0 * HD + col) = v0;
            if (r1 < NN) *(float2*)(C + (size_t)r1 * HD + col) = v1;
        }
    }
}

// ---------------- attn projections + fused deg histogram --------------------
// NN*32 threads == EE exactly: thread i also histograms edge i.
__global__ void attn_hist_kernel(const float* __restrict__ feat,
                                 const float* __restrict__ Wa_src,
                                 const float* __restrict__ Wa_dst,
                                 const int* __restrict__ dst) {
    int tg = blockIdx.x * blockDim.x + threadIdx.x;
    if (tg < EE) atomicAdd(&g_deg[__ldg(dst + tg)], 1);

    int gw = tg >> 5;
    int lane = threadIdx.x & 31;
    if (gw >= NN) return;
    float s0 = 0.f, s1 = 0.f, d0 = 0.f, d1 = 0.f;
#pragma unroll
    for (int j = 0; j < 8; j++) {
        int k = j * 32 + lane;
        float f = __ldg(feat + (size_t)gw * FIN + k);
        float2 ws = __ldg((const float2*)(Wa_src + k * HH));
        float2 wd = __ldg((const float2*)(Wa_dst + k * HH));
        s0 = fmaf(f, ws.x, s0); s1 = fmaf(f, ws.y, s1);
        d0 = fmaf(f, wd.x, d0); d1 = fmaf(f, wd.y, d1);
    }
    s0 = wsum(s0); s1 = wsum(s1); d0 = wsum(d0); d1 = wsum(d1);
    if (lane == 0) {
        *(float2*)(g_asrc + gw * HH) = make_float2(s0, s1);
        *(float2*)(g_adst + gw * HH) = make_float2(d0, d1);
    }
}

// ---------------- zero deg + sums -------------------------------------------
__global__ void zero_misc_kernel() {
    int i = blockIdx.x * blockDim.x + threadIdx.x;
    if (i < NN) g_deg[i] = 0;
    if (i < 2 * NHH) g_sum2[i] = 0.0f;
}

// ---------------- scan (1 block) ---------------------------------------------
__global__ void scan_kernel() {
    __shared__ int sp[1024];
    const int CH = 49;
    int t = threadIdx.x;
    int lo = t * CH, hi = min(lo + CH, NN);
    int s = 0;
    for (int i = lo; i < hi; i++) s += g_deg[i];
    sp[t] = s;
    __syncthreads();
    for (int o = 1; o < 1024; o <<= 1) {
        int v = (t >= o) ? sp[t - o] : 0;
        __syncthreads();
        sp[t] += v;
        __syncthreads();
    }
    int base = (t == 0) ? 0 : sp[t - 1];
    for (int i = lo; i < hi; i++) {
        g_off[i] = base; g_cur[i] = base; base += g_deg[i];
    }
    if (t == 1023) g_off[NN] = sp[1023];
}

// ---------------- pass1: exp + v2 segment sums + CSR scatter -----------------
__global__ void edge_pass1_kernel(const int* __restrict__ src,
                                  const int* __restrict__ dst) {
    int e = blockIdx.x * blockDim.x + threadIdx.x;
    if (e >= EE) return;
    int s = src[e], d = dst[e];
    float2 as = __ldg((const float2*)(g_asrc + s * HH));
    float2 ad = __ldg((const float2*)(g_adst + d * HH));
    float x0 = expf(leaky(as.x + ad.x));
    float x1 = expf(leaky(as.y + ad.y));
    int pos = atomicAdd(&g_cur[d], 1);
    g_csr_ed[pos] = make_float4(__int_as_float(s), x0, x1, 0.f);
    asm volatile("red.global.add.v2.f32 [%0], {%1,%2};"
                 :: "l"(g_sum2 + d * HH), "f"(x0), "f"(x1) : "memory");
    asm volatile("red.global.add.v2.f32 [%0], {%1,%2};"
                 :: "l"(g_sum2 + NHH + s * HH), "f"(x0), "f"(x1) : "memory");
}

// ---------------- fused hop: pull-aggregate + feat_trans ---------------------
// FIRST: also normalize edge weights inline and write them back for hops 1-2.
template <bool FIRST>
__global__ __launch_bounds__(256) void hop_agg_kernel(int k,
                               const float* __restrict__ scale,
                               const float* __restrict__ offset,
                               const float* __restrict__ pemb) {
    int node = blockIdx.x * (blockDim.x >> 5) + (threadIdx.x >> 5);
    if (node >= NN) return;
    int lane = threadIdx.x & 31;
    const float* hin = FIRST ? g_hsrc : g_h[(k + 1) & 1];

    float2 sd = make_float2(1.f, 1.f);
    if (FIRST) sd = *(const float2*)(g_sum2 + node * HH);

    int beg = g_off[node], end = g_off[node + 1];
    float4 acc = make_float4(0.f, 0.f, 0.f, 0.f);

    int j = beg;
    for (; j + 8 <= end; j += 8) {
        float4 r[8];
#pragma unroll
        for (int u = 0; u < 8; u++) r[u] = __ldg(g_csr_ed + j + u);
        float a0[8], a1[8];
#pragma unroll
        for (int u = 0; u < 8; u++) {
            if (FIRST) {
                int s = __float_as_int(r[u].x);
                float2 ss = __ldg((const float2*)(g_sum2 + NHH + s * HH));
                a0[u] = sqrtf(fmaxf(r[u].y / sd.x, 1e-9f) * fmaxf(r[u].y / ss.x, 1e-9f));
                a1[u] = sqrtf(fmaxf(r[u].z / sd.y, 1e-9f) * fmaxf(r[u].z / ss.y, 1e-9f));
                if (lane == 0)
                    g_csr_ed[j + u] = make_float4(r[u].x, a0[u], a1[u], 0.f);
            } else {
                a0[u] = r[u].y; a1[u] = r[u].z;
            }
        }
        float4 v[8];
#pragma unroll
        for (int u = 0; u < 8; u++) {
            int s = __float_as_int(r[u].x);
            v[u] = __ldg(((const float4*)(hin + (size_t)s * HD)) + lane);
        }
#pragma unroll
        for (int u = 0; u < 8; u++) {
            float a = (lane < 16) ? a0[u] : a1[u];
            acc.x = fmaf(a, v[u].x, acc.x);
            acc.y = fmaf(a, v[u].y, acc.y);
            acc.z = fmaf(a, v[u].z, acc.z);
            acc.w = fmaf(a, v[u].w, acc.w);
        }
    }
    for (; j < end; j++) {
        float4 r = __ldg(g_csr_ed + j);
        int s = __float_as_int(r.x);
        float a0, a1;
        if (FIRST) {
            float2 ss = __ldg((const float2*)(g_sum2 + NHH + s * HH));
            a0 = sqrtf(fmaxf(r.y / sd.x, 1e-9f) * fmaxf(r.y / ss.x, 1e-9f));
            a1 = sqrtf(fmaxf(r.z / sd.y, 1e-9f) * fmaxf(r.z / ss.y, 1e-9f));
            if (lane == 0)
                g_csr_ed[j] = make_float4(r.x, a0, a1, 0.f);
        } else {
            a0 = r.y; a1 = r.z;
        }
        float a = (lane < 16) ? a0 : a1;
        float4 v = __ldg(((const float4*)(hin + (size_t)s * HD)) + lane);
        acc.x = fmaf(a, v.x, acc.x);
        acc.y = fmaf(a, v.y, acc.y);
        acc.z = fmaf(a, v.z, acc.z);
        acc.w = fmaf(a, v.w, acc.w);
    }

    if (k < KK - 1)
        *(float4*)(g_h[k & 1] + (size_t)node * HD + lane * 4) = acc;

    float mean = hsum16(acc.x + acc.y + acc.z + acc.w) * (1.0f / DD);
    float dx = acc.x - mean, dy = acc.y - mean, dz = acc.z - mean, dw = acc.w - mean;
    float ssq = hsum16(dx * dx + dy * dy + dz * dz + dw * dw);
    float r = rsqrtf(ssq * (1.0f / DD) + 1e-9f);
    int h = lane >> 4;
    int base = (k + 1) * HD + h * DD + (lane & 15) * 4;
    float4 o;
    o.x = dx * scale[base + 0] * r + offset[base + 0] + pemb[base + 0];
    o.y = dy * scale[base + 1] * r + offset[base + 1] + pemb[base + 1];
    o.z = dz * scale[base + 2] * r + offset[base + 2] + pemb[base + 2];
    o.w = dw * scale[base + 3] * r + offset[base + 3] + pemb[base + 3];
    *(float4*)(g_hs[k] + (size_t)node * HD + lane * 4) = o;
}

// ---------------- hop attention + residual -> out ----------------------------
__global__ void final_kernel(const float* __restrict__ scale,
                             const float* __restrict__ offset,
                             const float* __restrict__ pemb,
                             const float* __restrict__ attn_l,
                             const float* __restrict__ attn_r,
                             float* __restrict__ out) {
    int gw = (blockIdx.x * blockDim.x + threadIdx.x) >> 5;
    int lane = threadIdx.x & 31;
    if (gw >= NHH) return;
    int h = gw & 1;

    const float* p = g_hsrc + (size_t)gw * DD;
    float x0 = p[lane], x1 = p[lane + 32];
    float mean = wsum(x0 + x1) * (1.0f / DD);
    float d0 = x0 - mean, d1 = x1 - mean;
    float var = wsum(d0 * d0 + d1 * d1) * (1.0f / DD) + 1e-9f;
    float r = rsqrtf(var);
    int b0 = h * DD;
    float f0 = d0 * scale[b0 + lane]      * r + offset[b0 + lane]      + pemb[b0 + lane];
    float f1 = d1 * scale[b0 + lane + 32] * r + offset[b0 + lane + 32] + pemb[b0 + lane + 32];
    float al = wsum(f0 * attn_l[h * DD + lane] + f1 * attn_l[h * DD + lane + 32]);

    float xs0[KK], xs1[KK], ha[KK];
    float ar0 = attn_r[h * DD + lane], ar1 = attn_r[h * DD + lane + 32];
#pragma unroll
    for (int k = 0; k < KK; k++) {
        xs0[k] = g_hs[k][(size_t)gw * DD + lane];
        xs1[k] = g_hs[k][(size_t)gw * DD + lane + 32];
        ha[k] = leaky(wsum(xs0[k] * ar0 + xs1[k] * ar1) + al);
    }
    float m = fmaxf(ha[0], fmaxf(ha[1], ha[2]));
    float w0 = expf(ha[0] - m), w1 = expf(ha[1] - m), w2 = expf(ha[2] - m);
    float inv = 1.0f / (w0 + w1 + w2);
    w0 *= inv; w1 *= inv; w2 *= inv;

    float o0 = xs0[0] * w0 + xs0[1] * w1 + xs0[2] * w2 + g_hdst[(size_t)gw * DD + lane];
    float o1 = xs1[0] * w0 + xs1[1] * w1 + xs1[2] * w2 + g_hdst[(size_t)gw * DD + lane + 32];
    out[(size_t)gw * DD + lane]      = o0;
    out[(size_t)gw * DD + lane + 32] = o1;
}

// ---------------- launch -----------------------------------------------------
extern "C" void kernel_launch(void* const* d_in, const int* in_sizes, int n_in,
                              void* d_out, int out_size) {
    const float* feat   = (const float*)d_in[0];
    const int*   src    = (const int*)d_in[1];
    const int*   dst    = (const int*)d_in[2];
    const float* W_src  = (const float*)d_in[3];
    const float* W_dst  = (const float*)d_in[4];
    const float* b_dst  = (const float*)d_in[5];
    const float* Wa_src = (const float*)d_in[6];
    const float* Wa_dst = (const float*)d_in[7];
    const float* scale  = (const float*)d_in[8];
    const float* offset = (const float*)d_in[9];
    const float* pemb   = (const float*)d_in[10];
    const float* hal    = (const float*)d_in[11];
    const float* har    = (const float*)d_in[12];
    float* out = (float*)d_out;

    // fork: GEMM runs on a side stream, overlapped with the edge chain.
    cudaStream_t s2;
    cudaStreamCreateWithFlags(&s2, cudaStreamNonBlocking);
    cudaEvent_t evRoot, evGemm;
    cudaEventCreateWithFlags(&evRoot, cudaEventDisableTiming);
    cudaEventCreateWithFlags(&evGemm, cudaEventDisableTiming);

    cudaEventRecord(evRoot, 0);
    cudaStreamWaitEvent(s2, evRoot, 0);
    dim3 ggrid((NN + 127) / 128, 2);
    gemm_tf32_kernel<<<ggrid, 256, 0, s2>>>(feat, W_src, W_dst, b_dst);
    cudaEventRecord(evGemm, s2);

    // main chain (default stream)
    zero_misc_kernel<<<(2 * NHH + 255) / 256, 256>>>();
    attn_hist_kernel<<<(NN * 32 + 255) / 256, 256>>>(feat, Wa_src, Wa_dst, dst);
    scan_kernel<<<1, 1024>>>();
    edge_pass1_kernel<<<(EE + 255) / 256, 256>>>(src, dst);

    // join: hops need both the CSR weights and g_hsrc
    cudaStreamWaitEvent(0, evGemm, 0);

    int node_blocks = (NN * 32 + 255) / 256;
    hop_agg_kernel<true><<<node_blocks, 256>>>(0, scale, offset, pemb);
    hop_agg_kernel<false><<<node_blocks, 256>>>(1, scale, offset, pemb);
    hop_agg_kernel<false><<<node_blocks, 256>>>(2, scale, offset, pemb);

    final_kernel<<<(NHH * 32 + 255) / 256, 256>>>(scale, offset, pemb, hal, har, out);
    // streams/events intentionally not destroyed while capture may be active
    // (kernel_launch is invoked only a handful of times; no device memory involved)
}